// round 14
// baseline (speedup 1.0000x reference)
#include <cuda_runtime.h>
#include <cstdint>

#define NTOK 98
#define NN2  (NTOK*NTOK)          // 9604
#define CDIM 192
#define NH   6
#define HD   32
#define NWIN 64
#define BTOT 4096
#define ROWS (BTOT*NTOK)          // 401408
#define QKVN (3*CDIM)             // 576
#define PER_TENSOR (BTOT*NH*NTOK*HD)   // 77,070,336

// ---- scratch ----
__device__ float g_q[PER_TENSOR];
__device__ float g_k[PER_TENSOR];
__device__ float g_v[PER_TENSOR];
__device__ float g_o[ROWS*CDIM];             // attention output, (b, n, C) layout
__device__ float g_bm[NH*NWIN*NN2];          // combined bias+mask, (h, w, i, j)

// ---- tf32 helpers ----
__device__ __forceinline__ uint32_t f2tf(float x) {
    uint32_t r; asm("cvt.rna.tf32.f32 %0, %1;" : "=r"(r) : "f"(x)); return r;
}
__device__ __forceinline__ void tf32_split(float x, uint32_t& big, uint32_t& small) {
    big = f2tf(x);
    small = f2tf(x - __uint_as_float(big));
}

#define MMA_TF32(d, a, b)                                                     \
    asm volatile(                                                             \
        "mma.sync.aligned.m16n8k8.row.col.f32.tf32.tf32.f32 "                 \
        "{%0,%1,%2,%3}, {%4,%5,%6,%7}, {%8,%9}, {%0,%1,%2,%3};"               \
        : "+f"(d[0]), "+f"(d[1]), "+f"(d[2]), "+f"(d[3])                      \
        : "r"(a[0]), "r"(a[1]), "r"(a[2]), "r"(a[3]), "r"(b[0]), "r"(b[1]))

// ============================================================
// Kernel 1: combined bias+mask table
// ============================================================
__global__ void bm_prep(const float* __restrict__ table, const int* __restrict__ rel,
                        const float* __restrict__ mask) {
    int idx = blockIdx.x * 256 + threadIdx.x;
    if (idx < NH * NWIN * NN2) {
        int h   = idx / (NWIN * NN2);
        int rem = idx - h * (NWIN * NN2);
        int w   = rem / NN2;
        int ij  = rem - w * NN2;
        g_bm[idx] = table[rel[ij] * NH + h] + mask[w * NN2 + ij];
    }
}

// ============================================================
// Kernel 2: QKV GEMM, 3xTF32 mma, hi/lo SPLIT AT SMEM STORE.
// CTA 128Mx64N, 8 warps (4Mx2N), warp tile 32x32, K-chunk 16, reg prefetch.
// ============================================================
#define PITCH 20

__global__ __launch_bounds__(256)
void qkv_gemm(const float* __restrict__ A, const float* __restrict__ W,
              const float* __restrict__ bvec) {
    __shared__ uint32_t Ash[128 * PITCH], Asl[128 * PITCH];
    __shared__ uint32_t Bsh[64 * PITCH],  Bsl[64 * PITCH];

    const int tid  = threadIdx.x;
    const int bM   = blockIdx.x * 128;
    const int bN   = blockIdx.y * 64;
    const int lane = tid & 31;
    const int wid  = tid >> 5;
    const int wm   = wid & 3;
    const int wn   = wid >> 2;

    const int arow = tid >> 1;                  // 0..127
    const int acol = (tid & 1) * 8;             // 0 or 8
    const int brow = tid & 63;
    const int bcol = (tid >> 6) * 4;
    const float* Ag = A + (size_t)(bM + arow) * CDIM + acol;
    const float* Wg = W + (size_t)(bN + brow) * CDIM + bcol;

    float acc[2][4][4];
#pragma unroll
    for (int mt = 0; mt < 2; mt++)
#pragma unroll
        for (int nt = 0; nt < 4; nt++)
#pragma unroll
            for (int q = 0; q < 4; q++) acc[mt][nt][q] = 0.f;

    const int g4 = lane >> 2;
    const int t4 = lane & 3;

    float4 pa0 = *(const float4*)(Ag);
    float4 pa1 = *(const float4*)(Ag + 4);
    float4 pb  = *(const float4*)(Wg);

    for (int c = 0; c < 12; c++) {
        // split + store into smem hi/lo planes
        {
            const float av[8] = {pa0.x, pa0.y, pa0.z, pa0.w, pa1.x, pa1.y, pa1.z, pa1.w};
#pragma unroll
            for (int e = 0; e < 8; e++) {
                uint32_t hb, lb;
                tf32_split(av[e], hb, lb);
                Ash[arow * PITCH + acol + e] = hb;
                Asl[arow * PITCH + acol + e] = lb;
            }
            const float bv[4] = {pb.x, pb.y, pb.z, pb.w};
#pragma unroll
            for (int e = 0; e < 4; e++) {
                uint32_t hb, lb;
                tf32_split(bv[e], hb, lb);
                Bsh[brow * PITCH + bcol + e] = hb;
                Bsl[brow * PITCH + bcol + e] = lb;
            }
        }
        __syncthreads();

        if (c < 11) {
            pa0 = *(const float4*)(Ag + (c + 1) * 16);
            pa1 = *(const float4*)(Ag + (c + 1) * 16 + 4);
            pb  = *(const float4*)(Wg + (c + 1) * 16);
        }

#pragma unroll
        for (int ks = 0; ks < 16; ks += 8) {
            uint32_t Ab[2][4], Asm[2][4];
#pragma unroll
            for (int mt = 0; mt < 2; mt++) {
                const int r = wm * 32 + mt * 16 + g4;
#pragma unroll
                for (int q = 0; q < 4; q++) {
                    int rr = r + (q & 1) * 8;
                    int cc = ks + t4 + (q >> 1) * 4;
                    Ab[mt][q]  = Ash[rr * PITCH + cc];
                    Asm[mt][q] = Asl[rr * PITCH + cc];
                }
            }
            uint32_t Bb[4][2], Bsm[4][2];
#pragma unroll
            for (int nt = 0; nt < 4; nt++) {
                const int nb = wn * 32 + nt * 8 + g4;
#pragma unroll
                for (int q = 0; q < 2; q++) {
                    int cc = ks + t4 + q * 4;
                    Bb[nt][q]  = Bsh[nb * PITCH + cc];
                    Bsm[nt][q] = Bsl[nb * PITCH + cc];
                }
            }
#pragma unroll
            for (int mt = 0; mt < 2; mt++)
#pragma unroll
                for (int nt = 0; nt < 4; nt++) {
                    MMA_TF32(acc[mt][nt], Ab[mt], Bb[nt]);
                    MMA_TF32(acc[mt][nt], Ab[mt], Bsm[nt]);
                    MMA_TF32(acc[mt][nt], Asm[mt], Bb[nt]);
                }
        }
        __syncthreads();
    }

    const float scale = 0.17677669529663687f;
#pragma unroll
    for (int mt = 0; mt < 2; mt++) {
        int r0 = bM + wm * 32 + mt * 16 + g4;
        int r1 = r0 + 8;
        int b0 = r0 / NTOK, n0 = r0 - b0 * NTOK;
        int b1 = r1 / NTOK, n1 = r1 - b1 * NTOK;
#pragma unroll
        for (int nt = 0; nt < 4; nt++) {
            int c0  = bN + wn * 32 + nt * 8 + t4 * 2;
            int t   = c0 / CDIM;
            int rem = c0 - t * CDIM;
            int hh  = rem >> 5;
            int d   = rem & 31;
            float* tgt = (t == 0) ? g_q : (t == 1) ? g_k : g_v;
            float sc   = (t == 0) ? scale : 1.0f;
            float bb0 = bvec[c0], bb1 = bvec[c0 + 1];
            float2 v0, v1;
            v0.x = (acc[mt][nt][0] + bb0) * sc;
            v0.y = (acc[mt][nt][1] + bb1) * sc;
            v1.x = (acc[mt][nt][2] + bb0) * sc;
            v1.y = (acc[mt][nt][3] + bb1) * sc;
            size_t o0 = (((size_t)b0 * NH + hh) * NTOK + n0) * HD + d;
            size_t o1 = (((size_t)b1 * NH + hh) * NTOK + n1) * HD + d;
            *(float2*)&tgt[o0] = v0;
            *(float2*)&tgt[o1] = v1;
        }
    }
}

// ============================================================
// Kernel 3: tensor-core attention with K/V hi/lo split at load.
// One CTA per (b,h), 224 threads (7 warps), warp = 16-row band.
// ============================================================
#define SPITCH 40
#define NT13 13

__global__ __launch_bounds__(224)
void attn_tc(int dummy) {
    __shared__ float    Qf[112 * SPITCH];
    __shared__ uint32_t Kh[104 * SPITCH], Kl[104 * SPITCH];
    __shared__ uint32_t Vh[104 * SPITCH], Vl[104 * SPITCH];

    const int bh = blockIdx.x;
    const int b  = bh / NH;
    const int h  = bh - b * NH;
    const int w  = b & (NWIN - 1);

    const float* Qp = g_q + (size_t)bh * NTOK * HD;
    const float* Kp = g_k + (size_t)bh * NTOK * HD;
    const float* Vp = g_v + (size_t)bh * NTOK * HD;

    const int tid = threadIdx.x;

    // zero pads (rows >= 98, cols 32..39) — zero both planes everywhere first
    for (int i = tid; i < 112 * SPITCH / 4; i += 224)
        *(float4*)&Qf[i * 4] = make_float4(0, 0, 0, 0);
    for (int i = tid; i < 104 * SPITCH / 4; i += 224) {
        *(uint4*)&Kh[i * 4] = make_uint4(0, 0, 0, 0);
        *(uint4*)&Kl[i * 4] = make_uint4(0, 0, 0, 0);
        *(uint4*)&Vh[i * 4] = make_uint4(0, 0, 0, 0);
        *(uint4*)&Vl[i * 4] = make_uint4(0, 0, 0, 0);
    }
    __syncthreads();

    for (int idx = tid; idx < NTOK * HD; idx += 224) {
        int r = idx >> 5, d = idx & 31;
        Qf[r * SPITCH + d] = Qp[idx];
        uint32_t hb, lb;
        tf32_split(Kp[idx], hb, lb);
        Kh[r * SPITCH + d] = hb;
        Kl[r * SPITCH + d] = lb;
        tf32_split(Vp[idx], hb, lb);
        Vh[r * SPITCH + d] = hb;
        Vl[r * SPITCH + d] = lb;
    }
    __syncthreads();

    const int warp = tid >> 5;
    const int lane = tid & 31;
    const int g4   = lane >> 2;
    const int t4   = lane & 3;

    // ---- Q fragments (split once) ----
    uint32_t Ab[4][4], Asm[4][4];
#pragma unroll
    for (int kq = 0; kq < 4; kq++)
#pragma unroll
        for (int q = 0; q < 4; q++) {
            int r = warp * 16 + g4 + (q & 1) * 8;
            int c = kq * 8 + t4 + (q >> 1) * 4;
            tf32_split(Qf[r * SPITCH + c], Ab[kq][q], Asm[kq][q]);
        }

    float acc[NT13][4];
#pragma unroll
    for (int nt = 0; nt < NT13; nt++)
#pragma unroll
        for (int q = 0; q < 4; q++) acc[nt][q] = 0.f;

#pragma unroll
    for (int nt = 0; nt < NT13; nt++) {
#pragma unroll
        for (int kq = 0; kq < 4; kq++) {
            uint32_t Bb[2], Bs[2];
#pragma unroll
            for (int q = 0; q < 2; q++) {
                int j = nt * 8 + g4;
                int c = kq * 8 + t4 + q * 4;
                Bb[q] = Kh[j * SPITCH + c];
                Bs[q] = Kl[j * SPITCH + c];
            }
            MMA_TF32(acc[nt], Ab[kq], Bb);
            MMA_TF32(acc[nt], Ab[kq], Bs);
            MMA_TF32(acc[nt], Asm[kq], Bb);
        }
    }

    // ---- bias+mask, padded-col masking ----
    const float* bmp = g_bm + (size_t)(h * NWIN + w) * NN2;
    const int r0 = warp * 16 + g4;
    const int r1 = r0 + 8;
#pragma unroll
    for (int nt = 0; nt < NT13; nt++) {
        int j = nt * 8 + t4 * 2;
        if (j < NTOK) {
            if (r0 < NTOK) {
                float2 m0 = *(const float2*)&bmp[r0 * NTOK + j];
                acc[nt][0] += m0.x; acc[nt][1] += m0.y;
            }
            if (r1 < NTOK) {
                float2 m1 = *(const float2*)&bmp[r1 * NTOK + j];
                acc[nt][2] += m1.x; acc[nt][3] += m1.y;
            }
        } else {
            acc[nt][0] = -1e30f; acc[nt][1] = -1e30f;
            acc[nt][2] = -1e30f; acc[nt][3] = -1e30f;
        }
    }

    // ---- softmax ----
    float mx0 = -1e30f, mx1 = -1e30f;
#pragma unroll
    for (int nt = 0; nt < NT13; nt++) {
        mx0 = fmaxf(mx0, fmaxf(acc[nt][0], acc[nt][1]));
        mx1 = fmaxf(mx1, fmaxf(acc[nt][2], acc[nt][3]));
    }
#pragma unroll
    for (int off = 1; off <= 2; off <<= 1) {
        mx0 = fmaxf(mx0, __shfl_xor_sync(0xffffffffu, mx0, off));
        mx1 = fmaxf(mx1, __shfl_xor_sync(0xffffffffu, mx1, off));
    }
    float s0 = 0.f, s1 = 0.f;
#pragma unroll
    for (int nt = 0; nt < NT13; nt++) {
        acc[nt][0] = __expf(acc[nt][0] - mx0);
        acc[nt][1] = __expf(acc[nt][1] - mx0);
        acc[nt][2] = __expf(acc[nt][2] - mx1);
        acc[nt][3] = __expf(acc[nt][3] - mx1);
        s0 += acc[nt][0] + acc[nt][1];
        s1 += acc[nt][2] + acc[nt][3];
    }
#pragma unroll
    for (int off = 1; off <= 2; off <<= 1) {
        s0 += __shfl_xor_sync(0xffffffffu, s0, off);
        s1 += __shfl_xor_sync(0xffffffffu, s1, off);
    }
    const float inv0 = 1.0f / s0, inv1 = 1.0f / s1;
#pragma unroll
    for (int nt = 0; nt < NT13; nt++) {
        acc[nt][0] *= inv0; acc[nt][1] *= inv0;
        acc[nt][2] *= inv1; acc[nt][3] *= inv1;
    }

    // ---- PV ----
    float out[4][4];
#pragma unroll
    for (int nt = 0; nt < 4; nt++)
#pragma unroll
        for (int q = 0; q < 4; q++) out[nt][q] = 0.f;

    const int basel = lane & ~3;
    const int l0 = basel + (t4 >> 1);
    const int l2 = l0 + 2;
    const bool hi = (t4 & 1);

#pragma unroll
    for (int kt = 0; kt < NT13; kt++) {
        float d0 = acc[kt][0], d1 = acc[kt][1], d2 = acc[kt][2], d3 = acc[kt][3];
        float p0a = __shfl_sync(0xffffffffu, d0, l0);
        float p0b = __shfl_sync(0xffffffffu, d1, l0);
        float p2a = __shfl_sync(0xffffffffu, d0, l2);
        float p2b = __shfl_sync(0xffffffffu, d1, l2);
        float p1a = __shfl_sync(0xffffffffu, d2, l0);
        float p1b = __shfl_sync(0xffffffffu, d3, l0);
        float p3a = __shfl_sync(0xffffffffu, d2, l2);
        float p3b = __shfl_sync(0xffffffffu, d3, l2);
        float a0 = hi ? p0b : p0a;
        float a1 = hi ? p1b : p1a;
        float a2 = hi ? p2b : p2a;
        float a3 = hi ? p3b : p3a;

        uint32_t Pb[4], Ps[4];
        tf32_split(a0, Pb[0], Ps[0]);
        tf32_split(a1, Pb[1], Ps[1]);
        tf32_split(a2, Pb[2], Ps[2]);
        tf32_split(a3, Pb[3], Ps[3]);

#pragma unroll
        for (int nt = 0; nt < 4; nt++) {
            uint32_t Vb[2], Vs[2];
#pragma unroll
            for (int q = 0; q < 2; q++) {
                int j = kt * 8 + t4 + q * 4;
                int d = nt * 8 + g4;
                Vb[q] = Vh[j * SPITCH + d];
                Vs[q] = Vl[j * SPITCH + d];
            }
            MMA_TF32(out[nt], Pb, Vb);
            MMA_TF32(out[nt], Pb, Vs);
            MMA_TF32(out[nt], Ps, Vb);
        }
    }

#pragma unroll
    for (int nt = 0; nt < 4; nt++) {
        int d = nt * 8 + 2 * t4;
        if (r0 < NTOK)
            *(float2*)&g_o[((size_t)(b * NTOK + r0)) * CDIM + h * HD + d] =
                make_float2(out[nt][0], out[nt][1]);
        if (r1 < NTOK)
            *(float2*)&g_o[((size_t)(b * NTOK + r1)) * CDIM + h * HD + d] =
                make_float2(out[nt][2], out[nt][3]);
    }
}

// ============================================================
// Kernel 4: projection GEMM, 3xTF32 mma, hi/lo split at store.
// ============================================================
__global__ __launch_bounds__(256)
void proj_gemm(const float* __restrict__ W, const float* __restrict__ bvec,
               float* __restrict__ C) {
    __shared__ uint32_t Ash[128 * PITCH], Asl[128 * PITCH];
    __shared__ uint32_t Bsh[64 * PITCH],  Bsl[64 * PITCH];

    const int tid  = threadIdx.x;
    const int bM   = blockIdx.x * 128;
    const int bN   = blockIdx.y * 64;
    const int lane = tid & 31;
    const int wid  = tid >> 5;
    const int wm   = wid & 3;
    const int wn   = wid >> 2;

    const int arow = tid >> 1;
    const int acol = (tid & 1) * 8;
    const int brow = tid & 63;
    const int bcol = (tid >> 6) * 4;
    const float* Ag = g_o + (size_t)(bM + arow) * CDIM + acol;
    const float* Wg = W   + (size_t)(bN + brow) * CDIM + bcol;

    float acc[2][4][4];
#pragma unroll
    for (int mt = 0; mt < 2; mt++)
#pragma unroll
        for (int nt = 0; nt < 4; nt++)
#pragma unroll
            for (int q = 0; q < 4; q++) acc[mt][nt][q] = 0.f;

    const int g4 = lane >> 2;
    const int t4 = lane & 3;

    float4 pa0 = *(const float4*)(Ag);
    float4 pa1 = *(const float4*)(Ag + 4);
    float4 pb  = *(const float4*)(Wg);

    for (int c = 0; c < 12; c++) {
        {
            const float av[8] = {pa0.x, pa0.y, pa0.z, pa0.w, pa1.x, pa1.y, pa1.z, pa1.w};
#pragma unroll
            for (int e = 0; e < 8; e++) {
                uint32_t hb, lb;
                tf32_split(av[e], hb, lb);
                Ash[arow * PITCH + acol + e] = hb;
                Asl[arow * PITCH + acol + e] = lb;
            }
            const float bv[4] = {pb.x, pb.y, pb.z, pb.w};
#pragma unroll
            for (int e = 0; e < 4; e++) {
                uint32_t hb, lb;
                tf32_split(bv[e], hb, lb);
                Bsh[brow * PITCH + bcol + e] = hb;
                Bsl[brow * PITCH + bcol + e] = lb;
            }
        }
        __syncthreads();

        if (c < 11) {
            pa0 = *(const float4*)(Ag + (c + 1) * 16);
            pa1 = *(const float4*)(Ag + (c + 1) * 16 + 4);
            pb  = *(const float4*)(Wg + (c + 1) * 16);
        }

#pragma unroll
        for (int ks = 0; ks < 16; ks += 8) {
            uint32_t Ab[2][4], Asm[2][4];
#pragma unroll
            for (int mt = 0; mt < 2; mt++) {
                const int r = wm * 32 + mt * 16 + g4;
#pragma unroll
                for (int q = 0; q < 4; q++) {
                    int rr = r + (q & 1) * 8;
                    int cc = ks + t4 + (q >> 1) * 4;
                    Ab[mt][q]  = Ash[rr * PITCH + cc];
                    Asm[mt][q] = Asl[rr * PITCH + cc];
                }
            }
            uint32_t Bb[4][2], Bsm[4][2];
#pragma unroll
            for (int nt = 0; nt < 4; nt++) {
                const int nb = wn * 32 + nt * 8 + g4;
#pragma unroll
                for (int q = 0; q < 2; q++) {
                    int cc = ks + t4 + q * 4;
                    Bb[nt][q]  = Bsh[nb * PITCH + cc];
                    Bsm[nt][q] = Bsl[nb * PITCH + cc];
                }
            }
#pragma unroll
            for (int mt = 0; mt < 2; mt++)
#pragma unroll
                for (int nt = 0; nt < 4; nt++) {
                    MMA_TF32(acc[mt][nt], Ab[mt], Bb[nt]);
                    MMA_TF32(acc[mt][nt], Ab[mt], Bsm[nt]);
                    MMA_TF32(acc[mt][nt], Asm[mt], Bb[nt]);
                }
        }
        __syncthreads();
    }

#pragma unroll
    for (int mt = 0; mt < 2; mt++) {
        int r0 = bM + wm * 32 + mt * 16 + g4;
        int r1 = r0 + 8;
#pragma unroll
        for (int nt = 0; nt < 4; nt++) {
            int c0 = bN + wn * 32 + nt * 8 + t4 * 2;
            float bb0 = bvec[c0], bb1 = bvec[c0 + 1];
            float2 v0, v1;
            v0.x = acc[mt][nt][0] + bb0;
            v0.y = acc[mt][nt][1] + bb1;
            v1.x = acc[mt][nt][2] + bb0;
            v1.y = acc[mt][nt][3] + bb1;
            *(float2*)&C[(size_t)r0 * CDIM + c0] = v0;
            *(float2*)&C[(size_t)r1 * CDIM + c0] = v1;
        }
    }
}

// ============================================================
extern "C" void kernel_launch(void* const* d_in, const int* in_sizes, int n_in,
                              void* d_out, int out_size) {
    const float* x      = (const float*)d_in[0];
    const float* mask   = (const float*)d_in[1];
    const float* qkv_w  = (const float*)d_in[2];
    const float* qkv_b  = (const float*)d_in[3];
    const float* proj_w = (const float*)d_in[4];
    const float* proj_b = (const float*)d_in[5];
    const float* rpb    = (const float*)d_in[6];
    const int*   rel    = (const int*)d_in[7];
    float* out = (float*)d_out;

    bm_prep<<<(NH * NWIN * NN2 + 255) / 256, 256>>>(rpb, rel, mask);

    dim3 g1(ROWS / 128, QKVN / 64);     // 3136 x 9
    qkv_gemm<<<g1, 256>>>(x, qkv_w, qkv_b);

    attn_tc<<<BTOT * NH, 224>>>(0);

    dim3 g2(ROWS / 128, CDIM / 64);     // 3136 x 3
    proj_gemm<<<g2, 256>>>(proj_w, proj_b, out);
}

// round 16
// speedup vs baseline: 1.2777x; 1.2777x over previous
#include <cuda_runtime.h>
#include <cstdint>

#define NTOK 98
#define NN2  (NTOK*NTOK)          // 9604
#define CDIM 192
#define NH   6
#define HD   32
#define NWIN 64
#define BTOT 4096
#define ROWS (BTOT*NTOK)          // 401408
#define QKVN (3*CDIM)             // 576
#define PER_TENSOR (BTOT*NH*NTOK*HD)   // 77,070,336

// ---- scratch ----
__device__ float g_q[PER_TENSOR];
__device__ float g_k[PER_TENSOR];
__device__ float g_v[PER_TENSOR];
__device__ float g_o[ROWS*CDIM];             // attention output, (b, n, C) layout
__device__ float g_bm[NH*NWIN*NN2];          // combined bias+mask, (h, w, i, j)

// ---- tf32 helpers ----
__device__ __forceinline__ uint32_t f2tf(float x) {
    uint32_t r; asm("cvt.rna.tf32.f32 %0, %1;" : "=r"(r) : "f"(x)); return r;
}
__device__ __forceinline__ void tf32_split(float x, uint32_t& big, uint32_t& small) {
    big = f2tf(x);
    small = f2tf(x - __uint_as_float(big));
}

#define MMA_TF32(d, a, b)                                                     \
    asm volatile(                                                             \
        "mma.sync.aligned.m16n8k8.row.col.f32.tf32.tf32.f32 "                 \
        "{%0,%1,%2,%3}, {%4,%5,%6,%7}, {%8,%9}, {%0,%1,%2,%3};"               \
        : "+f"(d[0]), "+f"(d[1]), "+f"(d[2]), "+f"(d[3])                      \
        : "r"(a[0]), "r"(a[1]), "r"(a[2]), "r"(a[3]), "r"(b[0]), "r"(b[1]))

// ============================================================
// Kernel 1: combined bias+mask table
// ============================================================
__global__ void bm_prep(const float* __restrict__ table, const int* __restrict__ rel,
                        const float* __restrict__ mask) {
    int idx = blockIdx.x * 256 + threadIdx.x;
    if (idx < NH * NWIN * NN2) {
        int h   = idx / (NWIN * NN2);
        int rem = idx - h * (NWIN * NN2);
        int w   = rem / NN2;
        int ij  = rem - w * NN2;
        g_bm[idx] = table[rel[ij] * NH + h] + mask[w * NN2 + ij];
    }
}

// ============================================================
// Kernel 2: QKV GEMM via 3xTF32 mma, R8 structure, PASS-MAJOR MMA order
// (same-accumulator distance 8 instead of 1).
// ============================================================
#define PITCH 20

__global__ __launch_bounds__(256)
void qkv_gemm(const float* __restrict__ A, const float* __restrict__ W,
              const float* __restrict__ bvec) {
    __shared__ float As[128 * PITCH];
    __shared__ float Bs[64 * PITCH];

    const int tid  = threadIdx.x;
    const int bM   = blockIdx.x * 128;
    const int bN   = blockIdx.y * 64;
    const int lane = tid & 31;
    const int wid  = tid >> 5;
    const int wm   = wid & 3;
    const int wn   = wid >> 2;

    const int arow = tid >> 1;
    const int acol = (tid & 1) * 8;
    const int brow = tid & 63;
    const int bcol = (tid >> 6) * 4;
    const float* Ag = A + (size_t)(bM + arow) * CDIM + acol;
    const float* Wg = W + (size_t)(bN + brow) * CDIM + bcol;

    float acc[2][4][4];
#pragma unroll
    for (int mt = 0; mt < 2; mt++)
#pragma unroll
        for (int nt = 0; nt < 4; nt++)
#pragma unroll
            for (int q = 0; q < 4; q++) acc[mt][nt][q] = 0.f;

    float4 pa0 = *(const float4*)(Ag);
    float4 pa1 = *(const float4*)(Ag + 4);
    float4 pb  = *(const float4*)(Wg);

    const int g4 = lane >> 2;
    const int t4 = lane & 3;

    for (int c = 0; c < 12; c++) {
        *(float4*)&As[arow * PITCH + acol]     = pa0;
        *(float4*)&As[arow * PITCH + acol + 4] = pa1;
        *(float4*)&Bs[brow * PITCH + bcol]     = pb;
        __syncthreads();

        if (c < 11) {
            pa0 = *(const float4*)(Ag + (c + 1) * 16);
            pa1 = *(const float4*)(Ag + (c + 1) * 16 + 4);
            pb  = *(const float4*)(Wg + (c + 1) * 16);
        }

#pragma unroll
        for (int ks = 0; ks < 16; ks += 8) {
            uint32_t Ab[2][4], Asm[2][4];
#pragma unroll
            for (int mt = 0; mt < 2; mt++) {
                const int r = wm * 32 + mt * 16 + g4;
#pragma unroll
                for (int q = 0; q < 4; q++) {
                    int rr = r + (q & 1) * 8;
                    int cc = ks + t4 + (q >> 1) * 4;
                    tf32_split(As[rr * PITCH + cc], Ab[mt][q], Asm[mt][q]);
                }
            }
            uint32_t Bb[4][2], Bsm[4][2];
#pragma unroll
            for (int nt = 0; nt < 4; nt++) {
                const int nb = wn * 32 + nt * 8 + g4;
#pragma unroll
                for (int q = 0; q < 2; q++) {
                    int cc = ks + t4 + q * 4;
                    tf32_split(Bs[nb * PITCH + cc], Bb[nt][q], Bsm[nt][q]);
                }
            }
            // pass-major: 8 independent MMAs per pass, same-acc distance = 8
#pragma unroll
            for (int mt = 0; mt < 2; mt++)
#pragma unroll
                for (int nt = 0; nt < 4; nt++)
                    MMA_TF32(acc[mt][nt], Ab[mt], Bb[nt]);
#pragma unroll
            for (int mt = 0; mt < 2; mt++)
#pragma unroll
                for (int nt = 0; nt < 4; nt++)
                    MMA_TF32(acc[mt][nt], Ab[mt], Bsm[nt]);
#pragma unroll
            for (int mt = 0; mt < 2; mt++)
#pragma unroll
                for (int nt = 0; nt < 4; nt++)
                    MMA_TF32(acc[mt][nt], Asm[mt], Bb[nt]);
        }
        __syncthreads();
    }

    const float scale = 0.17677669529663687f;
#pragma unroll
    for (int mt = 0; mt < 2; mt++) {
        int r0 = bM + wm * 32 + mt * 16 + g4;
        int r1 = r0 + 8;
        int b0 = r0 / NTOK, n0 = r0 - b0 * NTOK;
        int b1 = r1 / NTOK, n1 = r1 - b1 * NTOK;
#pragma unroll
        for (int nt = 0; nt < 4; nt++) {
            int c0  = bN + wn * 32 + nt * 8 + t4 * 2;
            int t   = c0 / CDIM;
            int rem = c0 - t * CDIM;
            int hh  = rem >> 5;
            int d   = rem & 31;
            float* tgt = (t == 0) ? g_q : (t == 1) ? g_k : g_v;
            float sc   = (t == 0) ? scale : 1.0f;
            float bb0 = bvec[c0], bb1 = bvec[c0 + 1];
            float2 v0, v1;
            v0.x = (acc[mt][nt][0] + bb0) * sc;
            v0.y = (acc[mt][nt][1] + bb1) * sc;
            v1.x = (acc[mt][nt][2] + bb0) * sc;
            v1.y = (acc[mt][nt][3] + bb1) * sc;
            size_t o0 = (((size_t)b0 * NH + hh) * NTOK + n0) * HD + d;
            size_t o1 = (((size_t)b1 * NH + hh) * NTOK + n1) * HD + d;
            *(float2*)&tgt[o0] = v0;
            *(float2*)&tgt[o1] = v1;
        }
    }
}

// ============================================================
// Kernel 3: tensor-core attention, R8 structure, reordered MMA chains.
// QK: nt-groups of 4, kq outer, pass-major inside (distance 4, was 12).
// PV: pass-major over nt (distance 4, was 1).
// ============================================================
#define SPITCH 40
#define NT13 13

__global__ __launch_bounds__(224)
void attn_tc(int dummy) {
    __shared__ float Qf[112 * SPITCH];
    __shared__ float Kf[104 * SPITCH];
    __shared__ float Vf[104 * SPITCH];

    const int bh = blockIdx.x;
    const int b  = bh / NH;
    const int h  = bh - b * NH;
    const int w  = b & (NWIN - 1);

    const float* Qp = g_q + (size_t)bh * NTOK * HD;
    const float* Kp = g_k + (size_t)bh * NTOK * HD;
    const float* Vp = g_v + (size_t)bh * NTOK * HD;

    const int tid = threadIdx.x;

    for (int i = tid; i < 112 * SPITCH / 4; i += 224) *(float4*)&Qf[i * 4] = make_float4(0, 0, 0, 0);
    for (int i = tid; i < 104 * SPITCH / 4; i += 224) {
        *(float4*)&Kf[i * 4] = make_float4(0, 0, 0, 0);
        *(float4*)&Vf[i * 4] = make_float4(0, 0, 0, 0);
    }
    __syncthreads();

    for (int idx = tid; idx < NTOK * HD; idx += 224) {
        int r = idx >> 5, d = idx & 31;
        Qf[r * SPITCH + d] = Qp[idx];
        Kf[r * SPITCH + d] = Kp[idx];
        Vf[r * SPITCH + d] = Vp[idx];
    }
    __syncthreads();

    const int warp = tid >> 5;
    const int lane = tid & 31;
    const int g4   = lane >> 2;
    const int t4   = lane & 3;

    // ---- Q fragments ----
    uint32_t Ab[4][4], Asm[4][4];
#pragma unroll
    for (int kq = 0; kq < 4; kq++)
#pragma unroll
        for (int q = 0; q < 4; q++) {
            int r = warp * 16 + g4 + (q & 1) * 8;
            int c = kq * 8 + t4 + (q >> 1) * 4;
            tf32_split(Qf[r * SPITCH + c], Ab[kq][q], Asm[kq][q]);
        }

    float acc[NT13][4];
#pragma unroll
    for (int nt = 0; nt < NT13; nt++)
#pragma unroll
        for (int q = 0; q < 4; q++) acc[nt][q] = 0.f;

    // ---- QK^T: nt-groups of 4, pass-major inside each kq ----
#pragma unroll
    for (int ng = 0; ng < 3; ng++) {
        const int nb0 = ng * 4;
#pragma unroll
        for (int kq = 0; kq < 4; kq++) {
            uint32_t Bb[4][2], Bs[4][2];
#pragma unroll
            for (int j = 0; j < 4; j++) {
                const int jj = (nb0 + j) * 8 + g4;
#pragma unroll
                for (int q = 0; q < 2; q++) {
                    int c = kq * 8 + t4 + q * 4;
                    tf32_split(Kf[jj * SPITCH + c], Bb[j][q], Bs[j][q]);
                }
            }
#pragma unroll
            for (int j = 0; j < 4; j++)
                MMA_TF32(acc[nb0 + j], Ab[kq], Bb[j]);
#pragma unroll
            for (int j = 0; j < 4; j++)
                MMA_TF32(acc[nb0 + j], Ab[kq], Bs[j]);
#pragma unroll
            for (int j = 0; j < 4; j++)
                MMA_TF32(acc[nb0 + j], Asm[kq], Bb[j]);
        }
    }
    // tail nt = 12
#pragma unroll
    for (int kq = 0; kq < 4; kq++) {
        uint32_t Bb[2], Bs[2];
#pragma unroll
        for (int q = 0; q < 2; q++) {
            int j = 12 * 8 + g4;
            int c = kq * 8 + t4 + q * 4;
            tf32_split(Kf[j * SPITCH + c], Bb[q], Bs[q]);
        }
        MMA_TF32(acc[12], Ab[kq], Bb);
        MMA_TF32(acc[12], Ab[kq], Bs);
        MMA_TF32(acc[12], Asm[kq], Bb);
    }

    // ---- bias+mask, padded-col masking ----
    const float* bmp = g_bm + (size_t)(h * NWIN + w) * NN2;
    const int r0 = warp * 16 + g4;
    const int r1 = r0 + 8;
#pragma unroll
    for (int nt = 0; nt < NT13; nt++) {
        int j = nt * 8 + t4 * 2;
        if (j < NTOK) {
            if (r0 < NTOK) {
                float2 m0 = *(const float2*)&bmp[r0 * NTOK + j];
                acc[nt][0] += m0.x; acc[nt][1] += m0.y;
            }
            if (r1 < NTOK) {
                float2 m1 = *(const float2*)&bmp[r1 * NTOK + j];
                acc[nt][2] += m1.x; acc[nt][3] += m1.y;
            }
        } else {
            acc[nt][0] = -1e30f; acc[nt][1] = -1e30f;
            acc[nt][2] = -1e30f; acc[nt][3] = -1e30f;
        }
    }

    // ---- softmax ----
    float mx0 = -1e30f, mx1 = -1e30f;
#pragma unroll
    for (int nt = 0; nt < NT13; nt++) {
        mx0 = fmaxf(mx0, fmaxf(acc[nt][0], acc[nt][1]));
        mx1 = fmaxf(mx1, fmaxf(acc[nt][2], acc[nt][3]));
    }
#pragma unroll
    for (int off = 1; off <= 2; off <<= 1) {
        mx0 = fmaxf(mx0, __shfl_xor_sync(0xffffffffu, mx0, off));
        mx1 = fmaxf(mx1, __shfl_xor_sync(0xffffffffu, mx1, off));
    }
    float s0 = 0.f, s1 = 0.f;
#pragma unroll
    for (int nt = 0; nt < NT13; nt++) {
        acc[nt][0] = __expf(acc[nt][0] - mx0);
        acc[nt][1] = __expf(acc[nt][1] - mx0);
        acc[nt][2] = __expf(acc[nt][2] - mx1);
        acc[nt][3] = __expf(acc[nt][3] - mx1);
        s0 += acc[nt][0] + acc[nt][1];
        s1 += acc[nt][2] + acc[nt][3];
    }
#pragma unroll
    for (int off = 1; off <= 2; off <<= 1) {
        s0 += __shfl_xor_sync(0xffffffffu, s0, off);
        s1 += __shfl_xor_sync(0xffffffffu, s1, off);
    }
    const float inv0 = 1.0f / s0, inv1 = 1.0f / s1;
#pragma unroll
    for (int nt = 0; nt < NT13; nt++) {
        acc[nt][0] *= inv0; acc[nt][1] *= inv0;
        acc[nt][2] *= inv1; acc[nt][3] *= inv1;
    }

    // ---- PV: pass-major over nt (distance 4) ----
    float out[4][4];
#pragma unroll
    for (int nt = 0; nt < 4; nt++)
#pragma unroll
        for (int q = 0; q < 4; q++) out[nt][q] = 0.f;

    const int basel = lane & ~3;
    const int l0 = basel + (t4 >> 1);
    const int l2 = l0 + 2;
    const bool hi = (t4 & 1);

#pragma unroll
    for (int kt = 0; kt < NT13; kt++) {
        float d0 = acc[kt][0], d1 = acc[kt][1], d2 = acc[kt][2], d3 = acc[kt][3];
        float p0a = __shfl_sync(0xffffffffu, d0, l0);
        float p0b = __shfl_sync(0xffffffffu, d1, l0);
        float p2a = __shfl_sync(0xffffffffu, d0, l2);
        float p2b = __shfl_sync(0xffffffffu, d1, l2);
        float p1a = __shfl_sync(0xffffffffu, d2, l0);
        float p1b = __shfl_sync(0xffffffffu, d3, l0);
        float p3a = __shfl_sync(0xffffffffu, d2, l2);
        float p3b = __shfl_sync(0xffffffffu, d3, l2);
        float a0 = hi ? p0b : p0a;
        float a1 = hi ? p1b : p1a;
        float a2 = hi ? p2b : p2a;
        float a3 = hi ? p3b : p3a;

        uint32_t Pb[4], Ps[4];
        tf32_split(a0, Pb[0], Ps[0]);
        tf32_split(a1, Pb[1], Ps[1]);
        tf32_split(a2, Pb[2], Ps[2]);
        tf32_split(a3, Pb[3], Ps[3]);

        uint32_t Vb[4][2], Vs[4][2];
#pragma unroll
        for (int nt = 0; nt < 4; nt++) {
#pragma unroll
            for (int q = 0; q < 2; q++) {
                int j = kt * 8 + t4 + q * 4;
                int d = nt * 8 + g4;
                tf32_split(Vf[j * SPITCH + d], Vb[nt][q], Vs[nt][q]);
            }
        }
#pragma unroll
        for (int nt = 0; nt < 4; nt++)
            MMA_TF32(out[nt], Pb, Vb[nt]);
#pragma unroll
        for (int nt = 0; nt < 4; nt++)
            MMA_TF32(out[nt], Pb, Vs[nt]);
#pragma unroll
        for (int nt = 0; nt < 4; nt++)
            MMA_TF32(out[nt], Ps, Vb[nt]);
    }

#pragma unroll
    for (int nt = 0; nt < 4; nt++) {
        int d = nt * 8 + 2 * t4;
        if (r0 < NTOK)
            *(float2*)&g_o[((size_t)(b * NTOK + r0)) * CDIM + h * HD + d] =
                make_float2(out[nt][0], out[nt][1]);
        if (r1 < NTOK)
            *(float2*)&g_o[((size_t)(b * NTOK + r1)) * CDIM + h * HD + d] =
                make_float2(out[nt][2], out[nt][3]);
    }
}

// ============================================================
// Kernel 4: projection GEMM via 3xTF32 mma, pass-major MMA order.
// ============================================================
__global__ __launch_bounds__(256)
void proj_gemm(const float* __restrict__ W, const float* __restrict__ bvec,
               float* __restrict__ C) {
    __shared__ float As[128 * PITCH];
    __shared__ float Bs[64 * PITCH];

    const int tid  = threadIdx.x;
    const int bM   = blockIdx.x * 128;
    const int bN   = blockIdx.y * 64;
    const int lane = tid & 31;
    const int wid  = tid >> 5;
    const int wm   = wid & 3;
    const int wn   = wid >> 2;

    const int arow = tid >> 1;
    const int acol = (tid & 1) * 8;
    const int brow = tid & 63;
    const int bcol = (tid >> 6) * 4;
    const float* Ag = g_o + (size_t)(bM + arow) * CDIM + acol;
    const float* Wg = W   + (size_t)(bN + brow) * CDIM + bcol;

    float acc[2][4][4];
#pragma unroll
    for (int mt = 0; mt < 2; mt++)
#pragma unroll
        for (int nt = 0; nt < 4; nt++)
#pragma unroll
            for (int q = 0; q < 4; q++) acc[mt][nt][q] = 0.f;

    float4 pa0 = *(const float4*)(Ag);
    float4 pa1 = *(const float4*)(Ag + 4);
    float4 pb  = *(const float4*)(Wg);

    const int g4 = lane >> 2;
    const int t4 = lane & 3;

    for (int c = 0; c < 12; c++) {
        *(float4*)&As[arow * PITCH + acol]     = pa0;
        *(float4*)&As[arow * PITCH + acol + 4] = pa1;
        *(float4*)&Bs[brow * PITCH + bcol]     = pb;
        __syncthreads();

        if (c < 11) {
            pa0 = *(const float4*)(Ag + (c + 1) * 16);
            pa1 = *(const float4*)(Ag + (c + 1) * 16 + 4);
            pb  = *(const float4*)(Wg + (c + 1) * 16);
        }

#pragma unroll
        for (int ks = 0; ks < 16; ks += 8) {
            uint32_t Ab[2][4], Asm[2][4];
#pragma unroll
            for (int mt = 0; mt < 2; mt++) {
                const int r = wm * 32 + mt * 16 + g4;
#pragma unroll
                for (int q = 0; q < 4; q++) {
                    int rr = r + (q & 1) * 8;
                    int cc = ks + t4 + (q >> 1) * 4;
                    tf32_split(As[rr * PITCH + cc], Ab[mt][q], Asm[mt][q]);
                }
            }
            uint32_t Bb[4][2], Bsm[4][2];
#pragma unroll
            for (int nt = 0; nt < 4; nt++) {
                const int nb = wn * 32 + nt * 8 + g4;
#pragma unroll
                for (int q = 0; q < 2; q++) {
                    int cc = ks + t4 + q * 4;
                    tf32_split(Bs[nb * PITCH + cc], Bb[nt][q], Bsm[nt][q]);
                }
            }
#pragma unroll
            for (int mt = 0; mt < 2; mt++)
#pragma unroll
                for (int nt = 0; nt < 4; nt++)
                    MMA_TF32(acc[mt][nt], Ab[mt], Bb[nt]);
#pragma unroll
            for (int mt = 0; mt < 2; mt++)
#pragma unroll
                for (int nt = 0; nt < 4; nt++)
                    MMA_TF32(acc[mt][nt], Ab[mt], Bsm[nt]);
#pragma unroll
            for (int mt = 0; mt < 2; mt++)
#pragma unroll
                for (int nt = 0; nt < 4; nt++)
                    MMA_TF32(acc[mt][nt], Asm[mt], Bb[nt]);
        }
        __syncthreads();
    }

#pragma unroll
    for (int mt = 0; mt < 2; mt++) {
        int r0 = bM + wm * 32 + mt * 16 + g4;
        int r1 = r0 + 8;
#pragma unroll
        for (int nt = 0; nt < 4; nt++) {
            int c0 = bN + wn * 32 + nt * 8 + t4 * 2;
            float bb0 = bvec[c0], bb1 = bvec[c0 + 1];
            float2 v0, v1;
            v0.x = acc[mt][nt][0] + bb0;
            v0.y = acc[mt][nt][1] + bb1;
            v1.x = acc[mt][nt][2] + bb0;
            v1.y = acc[mt][nt][3] + bb1;
            *(float2*)&C[(size_t)r0 * CDIM + c0] = v0;
            *(float2*)&C[(size_t)r1 * CDIM + c0] = v1;
        }
    }
}

// ============================================================
extern "C" void kernel_launch(void* const* d_in, const int* in_sizes, int n_in,
                              void* d_out, int out_size) {
    const float* x      = (const float*)d_in[0];
    const float* mask   = (const float*)d_in[1];
    const float* qkv_w  = (const float*)d_in[2];
    const float* qkv_b  = (const float*)d_in[3];
    const float* proj_w = (const float*)d_in[4];
    const float* proj_b = (const float*)d_in[5];
    const float* rpb    = (const float*)d_in[6];
    const int*   rel    = (const int*)d_in[7];
    float* out = (float*)d_out;

    bm_prep<<<(NH * NWIN * NN2 + 255) / 256, 256>>>(rpb, rel, mask);

    dim3 g1(ROWS / 128, QKVN / 64);     // 3136 x 9
    qkv_gemm<<<g1, 256>>>(x, qkv_w, qkv_b);

    attn_tc<<<BTOT * NH, 224>>>(0);

    dim3 g2(ROWS / 128, CDIM / 64);     // 3136 x 3
    proj_gemm<<<g2, 256>>>(proj_w, proj_b, out);
}